// round 3
// baseline (speedup 1.0000x reference)
#include <cuda_runtime.h>
#include <cuda_bf16.h>
#include <cstdint>

#define NN 30000
#define EE 480000
#define HSTR 288      // hcat row stride (max K)
#define FD 256        // ft row width (H*64)

// ---------------- scratch (device globals; no allocs allowed) ----------------
__device__ float g_hcat[NN * HSTR];   // [h | pe] per layer, tf32-rounded values
__device__ float g_ft[NN * FD];       // per-layer transformed features
__device__ float g_Wr[288 * 256];     // tf32-rounded weight matrix (per layer)
__device__ float g_a1[NN * 4];
__device__ float g_a2[NN * 4];
__device__ int   g_cnt[NN];
__device__ int   g_off[NN + 1];
__device__ int   g_csr_src[EE];

__device__ __forceinline__ uint32_t f2tf32(float v) {
    uint32_t t;
    asm("cvt.rna.tf32.f32 %0, %1;" : "=r"(t) : "f"(v));
    return t;
}

// ---------------- CSR build ----------------
__global__ void k_zero_cnt() {
    int i = blockIdx.x * blockDim.x + threadIdx.x;
    if (i < NN) g_cnt[i] = 0;
}

__global__ void k_count(const int* __restrict__ dst) {
    int e = blockIdx.x * blockDim.x + threadIdx.x;
    if (e < EE) atomicAdd(&g_cnt[dst[e]], 1);
}

__global__ void k_scan() {
    __shared__ int warp_sums[32];
    __shared__ int s_carry;
    int tid = threadIdx.x;
    int lane = tid & 31, wid = tid >> 5;
    if (tid == 0) s_carry = 0;
    __syncthreads();
    for (int base = 0; base < NN; base += 1024) {
        int i = base + tid;
        int v = (i < NN) ? g_cnt[i] : 0;
        int x = v;
        #pragma unroll
        for (int d = 1; d < 32; d <<= 1) {
            int y = __shfl_up_sync(0xffffffffu, x, d);
            if (lane >= d) x += y;
        }
        if (lane == 31) warp_sums[wid] = x;
        __syncthreads();
        if (wid == 0) {
            int s = warp_sums[lane];
            #pragma unroll
            for (int d = 1; d < 32; d <<= 1) {
                int y = __shfl_up_sync(0xffffffffu, s, d);
                if (lane >= d) s += y;
            }
            warp_sums[lane] = s;
        }
        __syncthreads();
        int carry = s_carry;
        int excl = x - v + (wid > 0 ? warp_sums[wid - 1] : 0);
        if (i < NN) {
            g_off[i] = carry + excl;
            g_cnt[i] = carry + excl;
        }
        int chunk_total = warp_sums[31];
        __syncthreads();
        if (tid == 0) s_carry = carry + chunk_total;
        __syncthreads();
    }
    if (threadIdx.x == 0) g_off[NN] = s_carry;
}

__global__ void k_place(const int* __restrict__ src, const int* __restrict__ dst) {
    int e = blockIdx.x * blockDim.x + threadIdx.x;
    if (e < EE) {
        int p = atomicAdd(&g_cnt[dst[e]], 1);
        g_csr_src[p] = src[e];
    }
}

// ---------------- hcat assembly (writes tf32-rounded values) ----------------
__global__ void k_copy_feat(const float* __restrict__ f) {
    int i = blockIdx.x * blockDim.x + threadIdx.x;
    if (i < NN * 128) {
        int n = i >> 7, c = i & 127;
        g_hcat[n * HSTR + c] = __uint_as_float(f2tf32(f[i]));
    }
}

__global__ void k_fill_pe(const float* __restrict__ pe, const int* __restrict__ pos, int col0) {
    int i = blockIdx.x * blockDim.x + threadIdx.x;
    if (i < NN * 32) {
        int n = i >> 5, c = i & 31;
        g_hcat[n * HSTR + col0 + c] = __uint_as_float(f2tf32(pe[pos[n] * 32 + c]));
    }
}

__global__ void k_round_w(const float* __restrict__ W, int n) {
    int i = blockIdx.x * blockDim.x + threadIdx.x;
    if (i < n) g_Wr[i] = __uint_as_float(f2tf32(W[i]));
}

// ---------------- TF32 GEMM with cp.async 2-stage pipeline ----------------
// g_ft = g_hcat[:, :K] @ Wr, Wr row-major [K,256]. Block 128x128, BK=16.
// 8 warps (4M x 2N), warp tile 32x64 -> 2x8 m16n8k8.
// As: [m][k] stride 20 (lane-permutation conflict-free), Bs: [k][n] stride 132.
#define BM 128
#define BN 128
#define BK 16
#define ASTR 20
#define BSTR 132

__device__ __forceinline__ void cpa16(uint32_t dst, const float* src, int sz) {
    asm volatile("cp.async.cg.shared.global [%0], [%1], 16, %2;\n"
                 :: "r"(dst), "l"(src), "r"(sz));
}

__global__ __launch_bounds__(256, 2) void k_gemm_tf32(int K) {
    __shared__ float As[2][BM * ASTR];
    __shared__ float Bs[2][BK * BSTR];
    int bm = blockIdx.y * BM;
    int bn = blockIdx.x * BN;
    int tid = threadIdx.x;
    int lane = tid & 31, warp = tid >> 5;
    int warpM = warp & 3, warpN = warp >> 2;
    int gid = lane >> 2, tig = lane & 3;

    float c[2][8][4] = {};

    // A: 512 16B-chunks (128 rows x 4), 2 per thread
    int ac = tid * 2;
    int ar0 = ac >> 2, akq0 = (ac & 3) * 4;
    int ar1 = (ac + 1) >> 2, akq1 = ((ac + 1) & 3) * 4;
    // B: 512 16B-chunks (16 rows x 32), 2 per thread
    int bk0 = ac >> 5, bnq0 = (ac & 31) * 4;
    int bk1 = (ac + 1) >> 5, bnq1 = ((ac + 1) & 31) * 4;

    int p0 = (bm + ar0) < NN ? 16 : 0;
    int p1 = (bm + ar1) < NN ? 16 : 0;
    const float* a_src0 = g_hcat + (size_t)(p0 ? bm + ar0 : 0) * HSTR + akq0;
    const float* a_src1 = g_hcat + (size_t)(p1 ? bm + ar1 : 0) * HSTR + akq1;
    const float* b_src0 = g_Wr + bk0 * 256 + bn + bnq0;
    const float* b_src1 = g_Wr + bk1 * 256 + bn + bnq1;

    uint32_t sA = (uint32_t)__cvta_generic_to_shared(&As[0][0]);
    uint32_t sB = (uint32_t)__cvta_generic_to_shared(&Bs[0][0]);
    uint32_t dA0 = sA + (ar0 * ASTR + akq0) * 4;
    uint32_t dA1 = sA + (ar1 * ASTR + akq1) * 4;
    uint32_t dB0 = sB + (bk0 * BSTR + bnq0) * 4;
    uint32_t dB1 = sB + (bk1 * BSTR + bnq1) * 4;
    const uint32_t stA = BM * ASTR * 4;
    const uint32_t stB = BK * BSTR * 4;

    int T = K / BK;

    // prologue: tile 0
    cpa16(dA0, a_src0, p0);
    cpa16(dA1, a_src1, p1);
    cpa16(dB0, b_src0, 16);
    cpa16(dB1, b_src1, 16);
    asm volatile("cp.async.commit_group;\n");

    for (int t = 0; t < T; t++) {
        if (t + 1 < T) {
            int st = (t + 1) & 1;
            int k0 = (t + 1) * BK;
            cpa16(dA0 + st * stA, a_src0 + k0, p0);
            cpa16(dA1 + st * stA, a_src1 + k0, p1);
            cpa16(dB0 + st * stB, b_src0 + k0 * 256, 16);
            cpa16(dB1 + st * stB, b_src1 + k0 * 256, 16);
            asm volatile("cp.async.commit_group;\n");
            asm volatile("cp.async.wait_group 1;\n");
        } else {
            asm volatile("cp.async.wait_group 0;\n");
        }
        __syncthreads();

        const float* Ac = As[t & 1];
        const float* Bc = Bs[t & 1];
        #pragma unroll
        for (int ks = 0; ks < BK; ks += 8) {
            uint32_t a[2][4], b[8][2];
            #pragma unroll
            for (int mt = 0; mt < 2; mt++) {
                int m0 = warpM * 32 + mt * 16 + gid;
                a[mt][0] = __float_as_uint(Ac[m0 * ASTR + ks + tig]);
                a[mt][1] = __float_as_uint(Ac[(m0 + 8) * ASTR + ks + tig]);
                a[mt][2] = __float_as_uint(Ac[m0 * ASTR + ks + tig + 4]);
                a[mt][3] = __float_as_uint(Ac[(m0 + 8) * ASTR + ks + tig + 4]);
            }
            #pragma unroll
            for (int nt = 0; nt < 8; nt++) {
                int n0 = warpN * 64 + nt * 8 + gid;
                b[nt][0] = __float_as_uint(Bc[(ks + tig) * BSTR + n0]);
                b[nt][1] = __float_as_uint(Bc[(ks + tig + 4) * BSTR + n0]);
            }
            #pragma unroll
            for (int mt = 0; mt < 2; mt++)
                #pragma unroll
                for (int nt = 0; nt < 8; nt++)
                    asm volatile(
                        "mma.sync.aligned.m16n8k8.row.col.f32.tf32.tf32.f32 "
                        "{%0,%1,%2,%3}, {%4,%5,%6,%7}, {%8,%9}, {%0,%1,%2,%3};"
                        : "+f"(c[mt][nt][0]), "+f"(c[mt][nt][1]),
                          "+f"(c[mt][nt][2]), "+f"(c[mt][nt][3])
                        : "r"(a[mt][0]), "r"(a[mt][1]), "r"(a[mt][2]), "r"(a[mt][3]),
                          "r"(b[nt][0]), "r"(b[nt][1]));
        }
        __syncthreads();
    }

    // epilogue
    #pragma unroll
    for (int mt = 0; mt < 2; mt++) {
        int row0 = bm + warpM * 32 + mt * 16 + gid;
        int row1 = row0 + 8;
        #pragma unroll
        for (int nt = 0; nt < 8; nt++) {
            int col = bn + warpN * 64 + nt * 8 + tig * 2;
            if (row0 < NN)
                *(float2*)(g_ft + row0 * FD + col) = make_float2(c[mt][nt][0], c[mt][nt][1]);
            if (row1 < NN)
                *(float2*)(g_ft + row1 * FD + col) = make_float2(c[mt][nt][2], c[mt][nt][3]);
        }
    }
}

// ---------------- attention logits ----------------
__global__ void k_attn(const float* __restrict__ al, const float* __restrict__ ar) {
    int gw = (blockIdx.x * blockDim.x + threadIdx.x) >> 5;
    int lane = threadIdx.x & 31;
    if (gw >= NN * 4) return;
    int n = gw >> 2, h = gw & 3;
    const float* f = g_ft + n * FD + h * 64;
    float v0 = f[lane], v1 = f[lane + 32];
    float s1 = v0 * al[h * 64 + lane] + v1 * al[h * 64 + lane + 32];
    float s2 = v0 * ar[h * 64 + lane] + v1 * ar[h * 64 + lane + 32];
    #pragma unroll
    for (int d = 16; d; d >>= 1) {
        s1 += __shfl_xor_sync(0xffffffffu, s1, d);
        s2 += __shfl_xor_sync(0xffffffffu, s2, d);
    }
    if (lane == 0) {
        g_a1[n * 4 + h] = s1;
        g_a2[n * 4 + h] = s2;
    }
}

// ---------------- edge phase: one warp per destination node ----------------
__global__ void k_edge(float* __restrict__ out, int final_layer) {
    int gw = (blockIdx.x * blockDim.x + threadIdx.x) >> 5;
    int lane = threadIdx.x & 31;
    if (gw >= NN) return;
    int n = gw;
    int h = lane >> 3;
    float a2h = g_a2[n * 4 + h];
    int beg = g_off[n], end = g_off[n + 1];

    float m = -1e30f;
    for (int i = beg; i < end; i++) {
        int s = g_csr_src[i];
        float e = g_a1[s * 4 + h] + a2h;
        e = e > 0.f ? e : 0.2f * e;
        m = fmaxf(m, e);
    }
    float ssum = 0.f;
    for (int i = beg; i < end; i++) {
        int s = g_csr_src[i];
        float e = g_a1[s * 4 + h] + a2h;
        e = e > 0.f ? e : 0.2f * e;
        ssum += __expf(e - m);
    }
    float inv = ssum > 0.f ? 1.0f / ssum : 0.f;

    float acc[8] = {0, 0, 0, 0, 0, 0, 0, 0};
    for (int i = beg; i < end; i++) {
        int s = g_csr_src[i];
        float e = g_a1[s * 4 + h] + a2h;
        e = e > 0.f ? e : 0.2f * e;
        float alpha = __expf(e - m) * inv;
        const float4* p = (const float4*)(g_ft + s * FD + lane * 8);
        float4 u = p[0], w = p[1];
        acc[0] += u.x * alpha; acc[1] += u.y * alpha;
        acc[2] += u.z * alpha; acc[3] += u.w * alpha;
        acc[4] += w.x * alpha; acc[5] += w.y * alpha;
        acc[6] += w.z * alpha; acc[7] += w.w * alpha;
    }

    if (final_layer) {
        #pragma unroll
        for (int j = 0; j < 8; j++) {
            acc[j] += __shfl_xor_sync(0xffffffffu, acc[j], 8);
            acc[j] += __shfl_xor_sync(0xffffffffu, acc[j], 16);
        }
        if (lane < 8) {
            #pragma unroll
            for (int j = 0; j < 8; j++)
                out[n * 64 + lane * 8 + j] = acc[j] * 0.25f;
        }
    } else {
        float* d = g_hcat + n * HSTR + lane * 8;
        #pragma unroll
        for (int j = 0; j < 8; j++) {
            float x = acc[j];
            x = x > 0.f ? x : expm1f(x);              // ELU
            d[j] = __uint_as_float(f2tf32(x));        // pre-round for next GEMM
        }
    }
}

// ---------------- launcher ----------------
extern "C" void kernel_launch(void* const* d_in, const int* in_sizes, int n_in,
                              void* d_out, int out_size) {
    const float* features = (const float*)d_in[0];
    const float* W0  = (const float*)d_in[1];
    const float* al0 = (const float*)d_in[2];
    const float* ar0 = (const float*)d_in[3];
    const float* pe0 = (const float*)d_in[4];
    const float* W1  = (const float*)d_in[5];
    const float* al1 = (const float*)d_in[6];
    const float* ar1 = (const float*)d_in[7];
    const float* pe1 = (const float*)d_in[8];
    const float* W2  = (const float*)d_in[9];
    const float* al2 = (const float*)d_in[10];
    const float* ar2 = (const float*)d_in[11];
    const float* pe2 = (const float*)d_in[12];
    const int* src = (const int*)d_in[13];
    const int* dst = (const int*)d_in[14];
    const int* pos = (const int*)d_in[15];
    float* out = (float*)d_out;

    k_zero_cnt<<<(NN + 255) / 256, 256>>>();
    k_count<<<(EE + 255) / 256, 256>>>(dst);
    k_scan<<<1, 1024>>>();
    k_place<<<(EE + 255) / 256, 256>>>(src, dst);

    k_copy_feat<<<(NN * 128 + 255) / 256, 256>>>(features);
    k_fill_pe<<<(NN * 32 + 255) / 256, 256>>>(pe0, pos, 128);

    dim3 ggrid((256 + BN - 1) / BN, (NN + BM - 1) / BM);
    int attn_blocks = (NN * 4 + 7) / 8;
    int edge_blocks = (NN + 7) / 8;

    // layer 0 (K=160)
    k_round_w<<<(160 * 256 + 255) / 256, 256>>>(W0, 160 * 256);
    k_gemm_tf32<<<ggrid, 256>>>(160);
    k_attn<<<attn_blocks, 256>>>(al0, ar0);
    k_edge<<<edge_blocks, 256>>>(out, 0);
    k_fill_pe<<<(NN * 32 + 255) / 256, 256>>>(pe1, pos, 256);

    // layer 1 (K=288)
    k_round_w<<<(288 * 256 + 255) / 256, 256>>>(W1, 288 * 256);
    k_gemm_tf32<<<ggrid, 256>>>(288);
    k_attn<<<attn_blocks, 256>>>(al1, ar1);
    k_edge<<<edge_blocks, 256>>>(out, 0);
    k_fill_pe<<<(NN * 32 + 255) / 256, 256>>>(pe2, pos, 256);

    // layer 2 (K=288)
    k_round_w<<<(288 * 256 + 255) / 256, 256>>>(W2, 288 * 256);
    k_gemm_tf32<<<ggrid, 256>>>(288);
    k_attn<<<attn_blocks, 256>>>(al2, ar2);
    k_edge<<<edge_blocks, 256>>>(out, 1);
}

// round 4
// speedup vs baseline: 1.1521x; 1.1521x over previous
#include <cuda_runtime.h>
#include <cuda_bf16.h>
#include <cstdint>

#define NN 30000
#define EE 480000
#define HSTR 288      // hcat row stride (max K)
#define FD 256        // ft row width (H*64)

// ---------------- scratch (device globals; no allocs allowed) ----------------
__device__ float g_hcat[NN * HSTR];     // [h | pe] per layer, tf32-rounded
__device__ float g_ft[NN * FD];         // per-layer transformed features
__device__ float g_Wr[3 * 288 * 256];   // tf32-rounded weights, all layers
__device__ float g_a1[NN * 4];
__device__ float g_a2[NN * 4];
__device__ int   g_cnt[NN];
__device__ int   g_off[NN + 1];
__device__ int   g_csr_src[EE];

__device__ __forceinline__ uint32_t f2tf32(float v) {
    uint32_t t;
    asm("cvt.rna.tf32.f32 %0, %1;" : "=r"(t) : "f"(v));
    return t;
}

// ---------------- hcat assembly (tf32-rounded) ----------------
__global__ void k_copy_feat(const float* __restrict__ f) {
    int i = blockIdx.x * blockDim.x + threadIdx.x;
    if (i < NN * 128) {
        int n = i >> 7, c = i & 127;
        g_hcat[n * HSTR + c] = __uint_as_float(f2tf32(f[i]));
    }
}

__global__ void k_fill_pe(const float* __restrict__ pe, const int* __restrict__ pos, int col0) {
    int i = blockIdx.x * blockDim.x + threadIdx.x;
    if (i < NN * 32) {
        int n = i >> 5, c = i & 31;
        g_hcat[n * HSTR + col0 + c] = __uint_as_float(f2tf32(pe[pos[n] * 32 + c]));
    }
}

// round all three W matrices at once
__global__ void k_round_all(const float* __restrict__ W0, const float* __restrict__ W1,
                            const float* __restrict__ W2) {
    int i = blockIdx.x * blockDim.x + threadIdx.x;
    const int n0 = 160 * 256, n12 = 288 * 256;
    if (i < n0)
        g_Wr[i] = __uint_as_float(f2tf32(W0[i]));
    if (i < n12) {
        g_Wr[288 * 256 + i]     = __uint_as_float(f2tf32(W1[i]));
        g_Wr[2 * 288 * 256 + i] = __uint_as_float(f2tf32(W2[i]));
    }
}

// ---------------- CSR build ----------------
__global__ void k_zero_cnt() {
    int i = blockIdx.x * blockDim.x + threadIdx.x;
    if (i < NN) g_cnt[i] = 0;
}

__global__ void k_count(const int* __restrict__ dst) {
    int e = blockIdx.x * blockDim.x + threadIdx.x;
    if (e < EE) atomicAdd(&g_cnt[dst[e]], 1);
}

__global__ void k_scan() {
    __shared__ int warp_sums[32];
    __shared__ int s_carry;
    int tid = threadIdx.x;
    int lane = tid & 31, wid = tid >> 5;
    if (tid == 0) s_carry = 0;
    __syncthreads();
    for (int base = 0; base < NN; base += 1024) {
        int i = base + tid;
        int v = (i < NN) ? g_cnt[i] : 0;
        int x = v;
        #pragma unroll
        for (int d = 1; d < 32; d <<= 1) {
            int y = __shfl_up_sync(0xffffffffu, x, d);
            if (lane >= d) x += y;
        }
        if (lane == 31) warp_sums[wid] = x;
        __syncthreads();
        if (wid == 0) {
            int s = warp_sums[lane];
            #pragma unroll
            for (int d = 1; d < 32; d <<= 1) {
                int y = __shfl_up_sync(0xffffffffu, s, d);
                if (lane >= d) s += y;
            }
            warp_sums[lane] = s;
        }
        __syncthreads();
        int carry = s_carry;
        int excl = x - v + (wid > 0 ? warp_sums[wid - 1] : 0);
        if (i < NN) {
            g_off[i] = carry + excl;
            g_cnt[i] = carry + excl;
        }
        int chunk_total = warp_sums[31];
        __syncthreads();
        if (tid == 0) s_carry = carry + chunk_total;
        __syncthreads();
    }
    if (threadIdx.x == 0) g_off[NN] = s_carry;
}

__global__ void k_place(const int* __restrict__ src, const int* __restrict__ dst) {
    int e = blockIdx.x * blockDim.x + threadIdx.x;
    if (e < EE) {
        int p = atomicAdd(&g_cnt[dst[e]], 1);
        g_csr_src[p] = src[e];
    }
}

// ---------------- TF32 GEMM + fused attention-logit epilogue ----------------
// g_ft = g_hcat[:, :K] @ Wr[layer], plus g_a1/g_a2 = ft . al/ar per (row, head).
// Block 128x128, BK=16, cp.async 2-stage. 8 warps (4M x 2N); each warp's
// 32x64 tile is exactly one head's 64 columns -> atomics-free a1/a2 writes.
#define BM 128
#define BN 128
#define BK 16
#define ASTR 20
#define BSTR 132

__device__ __forceinline__ void cpa16(uint32_t dst, const float* src, int sz) {
    asm volatile("cp.async.cg.shared.global [%0], [%1], 16, %2;\n"
                 :: "r"(dst), "l"(src), "r"(sz));
}

__global__ __launch_bounds__(256, 2) void k_gemm_tf32(const float* __restrict__ Wb, int K,
                                                      const float* __restrict__ al,
                                                      const float* __restrict__ ar) {
    __shared__ float As[2][BM * ASTR];
    __shared__ float Bs[2][BK * BSTR];
    int bm = blockIdx.y * BM;
    int bn = blockIdx.x * BN;
    int tid = threadIdx.x;
    int lane = tid & 31, warp = tid >> 5;
    int warpM = warp & 3, warpN = warp >> 2;
    int gid = lane >> 2, tig = lane & 3;

    float c[2][8][4] = {};

    int ac = tid * 2;
    int ar0i = ac >> 2, akq0 = (ac & 3) * 4;
    int ar1i = (ac + 1) >> 2, akq1 = ((ac + 1) & 3) * 4;
    int bk0 = ac >> 5, bnq0 = (ac & 31) * 4;
    int bk1 = (ac + 1) >> 5, bnq1 = ((ac + 1) & 31) * 4;

    int p0 = (bm + ar0i) < NN ? 16 : 0;
    int p1 = (bm + ar1i) < NN ? 16 : 0;
    const float* a_src0 = g_hcat + (size_t)(p0 ? bm + ar0i : 0) * HSTR + akq0;
    const float* a_src1 = g_hcat + (size_t)(p1 ? bm + ar1i : 0) * HSTR + akq1;
    const float* b_src0 = Wb + bk0 * 256 + bn + bnq0;
    const float* b_src1 = Wb + bk1 * 256 + bn + bnq1;

    uint32_t sA = (uint32_t)__cvta_generic_to_shared(&As[0][0]);
    uint32_t sB = (uint32_t)__cvta_generic_to_shared(&Bs[0][0]);
    uint32_t dA0 = sA + (ar0i * ASTR + akq0) * 4;
    uint32_t dA1 = sA + (ar1i * ASTR + akq1) * 4;
    uint32_t dB0 = sB + (bk0 * BSTR + bnq0) * 4;
    uint32_t dB1 = sB + (bk1 * BSTR + bnq1) * 4;
    const uint32_t stA = BM * ASTR * 4;
    const uint32_t stB = BK * BSTR * 4;

    int T = K / BK;

    cpa16(dA0, a_src0, p0);
    cpa16(dA1, a_src1, p1);
    cpa16(dB0, b_src0, 16);
    cpa16(dB1, b_src1, 16);
    asm volatile("cp.async.commit_group;\n");

    for (int t = 0; t < T; t++) {
        if (t + 1 < T) {
            int st = (t + 1) & 1;
            int k0 = (t + 1) * BK;
            cpa16(dA0 + st * stA, a_src0 + k0, p0);
            cpa16(dA1 + st * stA, a_src1 + k0, p1);
            cpa16(dB0 + st * stB, b_src0 + k0 * 256, 16);
            cpa16(dB1 + st * stB, b_src1 + k0 * 256, 16);
            asm volatile("cp.async.commit_group;\n");
            asm volatile("cp.async.wait_group 1;\n");
        } else {
            asm volatile("cp.async.wait_group 0;\n");
        }
        __syncthreads();

        const float* Ac = As[t & 1];
        const float* Bc = Bs[t & 1];
        #pragma unroll
        for (int ks = 0; ks < BK; ks += 8) {
            uint32_t a[2][4], b[8][2];
            #pragma unroll
            for (int mt = 0; mt < 2; mt++) {
                int m0 = warpM * 32 + mt * 16 + gid;
                a[mt][0] = __float_as_uint(Ac[m0 * ASTR + ks + tig]);
                a[mt][1] = __float_as_uint(Ac[(m0 + 8) * ASTR + ks + tig]);
                a[mt][2] = __float_as_uint(Ac[m0 * ASTR + ks + tig + 4]);
                a[mt][3] = __float_as_uint(Ac[(m0 + 8) * ASTR + ks + tig + 4]);
            }
            #pragma unroll
            for (int nt = 0; nt < 8; nt++) {
                int n0 = warpN * 64 + nt * 8 + gid;
                b[nt][0] = __float_as_uint(Bc[(ks + tig) * BSTR + n0]);
                b[nt][1] = __float_as_uint(Bc[(ks + tig + 4) * BSTR + n0]);
            }
            #pragma unroll
            for (int mt = 0; mt < 2; mt++)
                #pragma unroll
                for (int nt = 0; nt < 8; nt++)
                    asm volatile(
                        "mma.sync.aligned.m16n8k8.row.col.f32.tf32.tf32.f32 "
                        "{%0,%1,%2,%3}, {%4,%5,%6,%7}, {%8,%9}, {%0,%1,%2,%3};"
                        : "+f"(c[mt][nt][0]), "+f"(c[mt][nt][1]),
                          "+f"(c[mt][nt][2]), "+f"(c[mt][nt][3])
                        : "r"(a[mt][0]), "r"(a[mt][1]), "r"(a[mt][2]), "r"(a[mt][3]),
                          "r"(b[nt][0]), "r"(b[nt][1]));
        }
        __syncthreads();
    }

    // epilogue: store ft + fused a1/a2 row-dots (warp tile = one head)
    int h = blockIdx.x * 2 + warpN;
    const float* alh = al + h * 64;
    const float* arh = ar + h * 64;
    #pragma unroll
    for (int mt = 0; mt < 2; mt++) {
        int row0 = bm + warpM * 32 + mt * 16 + gid;
        int row1 = row0 + 8;
        float s1r0 = 0.f, s2r0 = 0.f, s1r1 = 0.f, s2r1 = 0.f;
        #pragma unroll
        for (int nt = 0; nt < 8; nt++) {
            int c64 = nt * 8 + tig * 2;
            int col = bn + warpN * 64 + c64;
            float l0 = alh[c64], l1 = alh[c64 + 1];
            float r0 = arh[c64], r1 = arh[c64 + 1];
            s1r0 += c[mt][nt][0] * l0 + c[mt][nt][1] * l1;
            s2r0 += c[mt][nt][0] * r0 + c[mt][nt][1] * r1;
            s1r1 += c[mt][nt][2] * l0 + c[mt][nt][3] * l1;
            s2r1 += c[mt][nt][2] * r0 + c[mt][nt][3] * r1;
            if (row0 < NN)
                *(float2*)(g_ft + row0 * FD + col) = make_float2(c[mt][nt][0], c[mt][nt][1]);
            if (row1 < NN)
                *(float2*)(g_ft + row1 * FD + col) = make_float2(c[mt][nt][2], c[mt][nt][3]);
        }
        // reduce over tig (lanes gid*4 + {0,1,2,3})
        #pragma unroll
        for (int d = 1; d < 4; d <<= 1) {
            s1r0 += __shfl_xor_sync(0xffffffffu, s1r0, d);
            s2r0 += __shfl_xor_sync(0xffffffffu, s2r0, d);
            s1r1 += __shfl_xor_sync(0xffffffffu, s1r1, d);
            s2r1 += __shfl_xor_sync(0xffffffffu, s2r1, d);
        }
        if (tig == 0) {
            if (row0 < NN) { g_a1[row0 * 4 + h] = s1r0; g_a2[row0 * 4 + h] = s2r0; }
            if (row1 < NN) { g_a1[row1 * 4 + h] = s1r1; g_a2[row1 * 4 + h] = s2r1; }
        }
    }
}

// ---------------- edge phase: one warp per destination node, 2 passes ----------------
// Also fills next layer's pe columns (cols 256..287 of g_hcat) when pe_next != 0.
__global__ void k_edge(float* __restrict__ out, int final_layer,
                       const float* __restrict__ pe_next, const int* __restrict__ pos) {
    int gw = (blockIdx.x * blockDim.x + threadIdx.x) >> 5;
    int lane = threadIdx.x & 31;
    if (gw >= NN) return;
    int n = gw;
    int h = lane >> 3;
    float a2h = g_a2[n * 4 + h];
    int beg = g_off[n], end = g_off[n + 1];

    // pass 1: online softmax (running max m, rescaled sum ssum)
    float m = -1e30f, ssum = 0.f;
    #pragma unroll 2
    for (int i = beg; i < end; i++) {
        int s = g_csr_src[i];
        float e = g_a1[s * 4 + h] + a2h;
        e = e > 0.f ? e : 0.2f * e;
        float mn = fmaxf(m, e);
        ssum = ssum * __expf(m - mn) + __expf(e - mn);
        m = mn;
    }
    float inv = ssum > 0.f ? 1.0f / ssum : 0.f;

    // pass 2: weighted gather-accumulate
    float acc[8] = {0, 0, 0, 0, 0, 0, 0, 0};
    #pragma unroll 2
    for (int i = beg; i < end; i++) {
        int s = g_csr_src[i];
        float e = g_a1[s * 4 + h] + a2h;
        e = e > 0.f ? e : 0.2f * e;
        float alpha = __expf(e - m) * inv;
        const float4* p = (const float4*)(g_ft + s * FD + lane * 8);
        float4 u = p[0], w = p[1];
        acc[0] += u.x * alpha; acc[1] += u.y * alpha;
        acc[2] += u.z * alpha; acc[3] += u.w * alpha;
        acc[4] += w.x * alpha; acc[5] += w.y * alpha;
        acc[6] += w.z * alpha; acc[7] += w.w * alpha;
    }

    if (final_layer) {
        #pragma unroll
        for (int j = 0; j < 8; j++) {
            acc[j] += __shfl_xor_sync(0xffffffffu, acc[j], 8);
            acc[j] += __shfl_xor_sync(0xffffffffu, acc[j], 16);
        }
        if (lane < 8) {
            #pragma unroll
            for (int j = 0; j < 8; j++)
                out[n * 64 + lane * 8 + j] = acc[j] * 0.25f;
        }
    } else {
        float* d = g_hcat + n * HSTR + lane * 8;
        #pragma unroll
        for (int j = 0; j < 8; j++) {
            float x = acc[j];
            x = x > 0.f ? x : expm1f(x);              // ELU
            d[j] = __uint_as_float(f2tf32(x));        // pre-round for next GEMM
        }
        // fused pe fill for next layer (cols 256..287)
        g_hcat[n * HSTR + 256 + lane] =
            __uint_as_float(f2tf32(pe_next[pos[n] * 32 + lane]));
    }
}

// ---------------- launcher ----------------
extern "C" void kernel_launch(void* const* d_in, const int* in_sizes, int n_in,
                              void* d_out, int out_size) {
    const float* features = (const float*)d_in[0];
    const float* W0  = (const float*)d_in[1];
    const float* al0 = (const float*)d_in[2];
    const float* ar0 = (const float*)d_in[3];
    const float* pe0 = (const float*)d_in[4];
    const float* W1  = (const float*)d_in[5];
    const float* al1 = (const float*)d_in[6];
    const float* ar1 = (const float*)d_in[7];
    const float* pe1 = (const float*)d_in[8];
    const float* W2  = (const float*)d_in[9];
    const float* al2 = (const float*)d_in[10];
    const float* ar2 = (const float*)d_in[11];
    const float* pe2 = (const float*)d_in[12];
    const int* src = (const int*)d_in[13];
    const int* dst = (const int*)d_in[14];
    const int* pos = (const int*)d_in[15];
    float* out = (float*)d_out;

    float* Wr0 = nullptr; cudaGetSymbolAddress((void**)&Wr0, g_Wr);
    float* Wr1 = Wr0 + 288 * 256;
    float* Wr2 = Wr0 + 2 * 288 * 256;

    dim3 ggrid(2, (NN + BM - 1) / BM);
    int edge_blocks = (NN + 7) / 8;

    // Ordered so the GEMM is the 4th launch (ncu capture lands on it).
    k_copy_feat<<<(NN * 128 + 255) / 256, 256>>>(features);               // 1
    k_fill_pe<<<(NN * 32 + 255) / 256, 256>>>(pe0, pos, 128);             // 2
    k_round_all<<<(288 * 256 + 255) / 256, 256>>>(W0, W1, W2);            // 3
    k_gemm_tf32<<<ggrid, 256>>>(Wr0, 160, al0, ar0);                      // 4  <- profiled

    // CSR build (independent of GEMM; needed before first k_edge)
    k_zero_cnt<<<(NN + 255) / 256, 256>>>();                              // 5
    k_count<<<(EE + 255) / 256, 256>>>(dst);                              // 6
    k_scan<<<1, 1024>>>();                                                // 7
    k_place<<<(EE + 255) / 256, 256>>>(src, dst);                         // 8

    k_edge<<<edge_blocks, 256>>>(out, 0, pe1, pos);                       // 9

    k_gemm_tf32<<<ggrid, 256>>>(Wr1, 288, al1, ar1);                      // 10
    k_edge<<<edge_blocks, 256>>>(out, 0, pe2, pos);                       // 11

    k_gemm_tf32<<<ggrid, 256>>>(Wr2, 288, al2, ar2);                      // 12
    k_edge<<<edge_blocks, 256>>>(out, 1, nullptr, nullptr);               // 13
}

// round 5
// speedup vs baseline: 1.2817x; 1.1125x over previous
#include <cuda_runtime.h>
#include <cuda_bf16.h>
#include <cstdint>

#define NN 30000
#define EE 480000
#define HSTR 288      // hcat row stride (max K)
#define FD 256        // ft row width (H*64)

// ---------------- scratch (device globals; no allocs allowed) ----------------
__device__ float g_hcat[NN * HSTR];     // [h | pe] per layer, tf32-rounded
__device__ float g_ft[NN * FD];         // per-layer transformed features
__device__ float g_Wr[3 * 288 * 256];   // tf32-rounded weights, all layers
__device__ float g_a1[NN * 4];
__device__ float g_a2[NN * 4];
__device__ int   g_cnt[NN];
__device__ int   g_off[NN + 1];
__device__ int   g_csr_src[EE];

__device__ __forceinline__ uint32_t f2tf32(float v) {
    uint32_t t;
    asm("cvt.rna.tf32.f32 %0, %1;" : "=r"(t) : "f"(v));
    return t;
}

// ---------------- hcat assembly (tf32-rounded) ----------------
__global__ void k_copy_feat(const float* __restrict__ f) {
    int i = blockIdx.x * blockDim.x + threadIdx.x;
    if (i < NN * 128) {
        int n = i >> 7, c = i & 127;
        g_hcat[n * HSTR + c] = __uint_as_float(f2tf32(f[i]));
    }
}

__global__ void k_fill_pe(const float* __restrict__ pe, const int* __restrict__ pos, int col0) {
    int i = blockIdx.x * blockDim.x + threadIdx.x;
    if (i < NN * 32) {
        int n = i >> 5, c = i & 31;
        g_hcat[n * HSTR + col0 + c] = __uint_as_float(f2tf32(pe[pos[n] * 32 + c]));
    }
}

__global__ void k_round_all(const float* __restrict__ W0, const float* __restrict__ W1,
                            const float* __restrict__ W2) {
    int i = blockIdx.x * blockDim.x + threadIdx.x;
    const int n0 = 160 * 256, n12 = 288 * 256;
    if (i < n0)
        g_Wr[i] = __uint_as_float(f2tf32(W0[i]));
    if (i < n12) {
        g_Wr[288 * 256 + i]     = __uint_as_float(f2tf32(W1[i]));
        g_Wr[2 * 288 * 256 + i] = __uint_as_float(f2tf32(W2[i]));
    }
}

// ---------------- CSR build ----------------
__global__ void k_zero_cnt() {
    int i = blockIdx.x * blockDim.x + threadIdx.x;
    if (i < NN) g_cnt[i] = 0;
}

__global__ void k_count(const int* __restrict__ dst) {
    int e = blockIdx.x * blockDim.x + threadIdx.x;
    if (e < EE) atomicAdd(&g_cnt[dst[e]], 1);
}

__global__ void k_scan() {
    __shared__ int warp_sums[32];
    __shared__ int s_carry;
    int tid = threadIdx.x;
    int lane = tid & 31, wid = tid >> 5;
    if (tid == 0) s_carry = 0;
    __syncthreads();
    for (int base = 0; base < NN; base += 1024) {
        int i = base + tid;
        int v = (i < NN) ? g_cnt[i] : 0;
        int x = v;
        #pragma unroll
        for (int d = 1; d < 32; d <<= 1) {
            int y = __shfl_up_sync(0xffffffffu, x, d);
            if (lane >= d) x += y;
        }
        if (lane == 31) warp_sums[wid] = x;
        __syncthreads();
        if (wid == 0) {
            int s = warp_sums[lane];
            #pragma unroll
            for (int d = 1; d < 32; d <<= 1) {
                int y = __shfl_up_sync(0xffffffffu, s, d);
                if (lane >= d) s += y;
            }
            warp_sums[lane] = s;
        }
        __syncthreads();
        int carry = s_carry;
        int excl = x - v + (wid > 0 ? warp_sums[wid - 1] : 0);
        if (i < NN) {
            g_off[i] = carry + excl;
            g_cnt[i] = carry + excl;
        }
        int chunk_total = warp_sums[31];
        __syncthreads();
        if (tid == 0) s_carry = carry + chunk_total;
        __syncthreads();
    }
    if (threadIdx.x == 0) g_off[NN] = s_carry;
}

__global__ void k_place(const int* __restrict__ src, const int* __restrict__ dst) {
    int e = blockIdx.x * blockDim.x + threadIdx.x;
    if (e < EE) {
        int p = atomicAdd(&g_cnt[dst[e]], 1);
        g_csr_src[p] = src[e];
    }
}

// ---------------- TF32 GEMM + fused attention-logit epilogue ----------------
// Block 128x128, BK=16, cp.async 2-stage. 4 warps (2M x 2N), warp tile 64x64
// -> LDS/MMA = 1.0 (vs 1.5 before). BSTR=136 -> conflict-free B-frag reads.
#define BM 128
#define BN 128
#define BK 16
#define ASTR 20
#define BSTR 136

__device__ __forceinline__ void cpa16(uint32_t dst, const float* src, int sz) {
    asm volatile("cp.async.cg.shared.global [%0], [%1], 16, %2;\n"
                 :: "r"(dst), "l"(src), "r"(sz));
}

__global__ __launch_bounds__(128, 2) void k_gemm_tf32(const float* __restrict__ Wb, int K,
                                                      const float* __restrict__ al,
                                                      const float* __restrict__ ar) {
    __shared__ float As[2][BM * ASTR];
    __shared__ float Bs[2][BK * BSTR];
    int bm = blockIdx.y * BM;
    int bn = blockIdx.x * BN;
    int tid = threadIdx.x;
    int lane = tid & 31, warp = tid >> 5;
    int warpM = warp & 1, warpN = warp >> 1;     // 2 x 2
    int gid = lane >> 2, tig = lane & 3;

    float c[4][8][4] = {};

    // per-thread cp.async chunk lists: 4 A chunks + 4 B chunks (16B each)
    int arow[4], akq[4], apred[4];
    const float* asrc[4];
    uint32_t adst[4];
    int bkk[4], bnq[4];
    const float* bsrc[4];
    uint32_t bdst[4];
    uint32_t sA = (uint32_t)__cvta_generic_to_shared(&As[0][0]);
    uint32_t sB = (uint32_t)__cvta_generic_to_shared(&Bs[0][0]);
    #pragma unroll
    for (int j = 0; j < 4; j++) {
        int ch = tid + j * 128;
        arow[j] = ch >> 2; akq[j] = (ch & 3) * 4;
        apred[j] = (bm + arow[j]) < NN ? 16 : 0;
        asrc[j] = g_hcat + (size_t)(apred[j] ? bm + arow[j] : 0) * HSTR + akq[j];
        adst[j] = sA + (arow[j] * ASTR + akq[j]) * 4;
        bkk[j] = ch >> 5; bnq[j] = (ch & 31) * 4;
        bsrc[j] = Wb + bkk[j] * 256 + bn + bnq[j];
        bdst[j] = sB + (bkk[j] * BSTR + bnq[j]) * 4;
    }
    const uint32_t stA = BM * ASTR * 4;
    const uint32_t stB = BK * BSTR * 4;

    int T = K / BK;

    // prologue: tile 0
    #pragma unroll
    for (int j = 0; j < 4; j++) cpa16(adst[j], asrc[j], apred[j]);
    #pragma unroll
    for (int j = 0; j < 4; j++) cpa16(bdst[j], bsrc[j], 16);
    asm volatile("cp.async.commit_group;\n");

    for (int t = 0; t < T; t++) {
        if (t + 1 < T) {
            int st = (t + 1) & 1;
            int k0 = (t + 1) * BK;
            #pragma unroll
            for (int j = 0; j < 4; j++) cpa16(adst[j] + st * stA, asrc[j] + k0, apred[j]);
            #pragma unroll
            for (int j = 0; j < 4; j++) cpa16(bdst[j] + st * stB, bsrc[j] + k0 * 256, 16);
            asm volatile("cp.async.commit_group;\n");
            asm volatile("cp.async.wait_group 1;\n");
        } else {
            asm volatile("cp.async.wait_group 0;\n");
        }
        __syncthreads();

        const float* Ac = As[t & 1];
        const float* Bc = Bs[t & 1];
        #pragma unroll
        for (int ks = 0; ks < BK; ks += 8) {
            uint32_t a[4][4], b[8][2];
            #pragma unroll
            for (int mt = 0; mt < 4; mt++) {
                int m0 = warpM * 64 + mt * 16 + gid;
                a[mt][0] = __float_as_uint(Ac[m0 * ASTR + ks + tig]);
                a[mt][1] = __float_as_uint(Ac[(m0 + 8) * ASTR + ks + tig]);
                a[mt][2] = __float_as_uint(Ac[m0 * ASTR + ks + tig + 4]);
                a[mt][3] = __float_as_uint(Ac[(m0 + 8) * ASTR + ks + tig + 4]);
            }
            #pragma unroll
            for (int nt = 0; nt < 8; nt++) {
                int n0 = warpN * 64 + nt * 8 + gid;
                b[nt][0] = __float_as_uint(Bc[(ks + tig) * BSTR + n0]);
                b[nt][1] = __float_as_uint(Bc[(ks + tig + 4) * BSTR + n0]);
            }
            #pragma unroll
            for (int mt = 0; mt < 4; mt++)
                #pragma unroll
                for (int nt = 0; nt < 8; nt++)
                    asm volatile(
                        "mma.sync.aligned.m16n8k8.row.col.f32.tf32.tf32.f32 "
                        "{%0,%1,%2,%3}, {%4,%5,%6,%7}, {%8,%9}, {%0,%1,%2,%3};"
                        : "+f"(c[mt][nt][0]), "+f"(c[mt][nt][1]),
                          "+f"(c[mt][nt][2]), "+f"(c[mt][nt][3])
                        : "r"(a[mt][0]), "r"(a[mt][1]), "r"(a[mt][2]), "r"(a[mt][3]),
                          "r"(b[nt][0]), "r"(b[nt][1]));
        }
        __syncthreads();
    }

    // epilogue: store ft + fused a1/a2 row-dots (warp tile = one head's 64 cols)
    int h = blockIdx.x * 2 + warpN;
    const float* alh = al + h * 64;
    const float* arh = ar + h * 64;
    float lw[8][2], rw[8][2];
    #pragma unroll
    for (int nt = 0; nt < 8; nt++) {
        int c64 = nt * 8 + tig * 2;
        lw[nt][0] = alh[c64]; lw[nt][1] = alh[c64 + 1];
        rw[nt][0] = arh[c64]; rw[nt][1] = arh[c64 + 1];
    }
    #pragma unroll
    for (int mt = 0; mt < 4; mt++) {
        int row0 = bm + warpM * 64 + mt * 16 + gid;
        int row1 = row0 + 8;
        float s1r0 = 0.f, s2r0 = 0.f, s1r1 = 0.f, s2r1 = 0.f;
        #pragma unroll
        for (int nt = 0; nt < 8; nt++) {
            int col = bn + warpN * 64 + nt * 8 + tig * 2;
            s1r0 += c[mt][nt][0] * lw[nt][0] + c[mt][nt][1] * lw[nt][1];
            s2r0 += c[mt][nt][0] * rw[nt][0] + c[mt][nt][1] * rw[nt][1];
            s1r1 += c[mt][nt][2] * lw[nt][0] + c[mt][nt][3] * lw[nt][1];
            s2r1 += c[mt][nt][2] * rw[nt][0] + c[mt][nt][3] * rw[nt][1];
            if (row0 < NN)
                *(float2*)(g_ft + row0 * FD + col) = make_float2(c[mt][nt][0], c[mt][nt][1]);
            if (row1 < NN)
                *(float2*)(g_ft + row1 * FD + col) = make_float2(c[mt][nt][2], c[mt][nt][3]);
        }
        #pragma unroll
        for (int d = 1; d < 4; d <<= 1) {
            s1r0 += __shfl_xor_sync(0xffffffffu, s1r0, d);
            s2r0 += __shfl_xor_sync(0xffffffffu, s2r0, d);
            s1r1 += __shfl_xor_sync(0xffffffffu, s1r1, d);
            s2r1 += __shfl_xor_sync(0xffffffffu, s2r1, d);
        }
        if (tig == 0) {
            if (row0 < NN) { g_a1[row0 * 4 + h] = s1r0; g_a2[row0 * 4 + h] = s2r0; }
            if (row1 < NN) { g_a1[row1 * 4 + h] = s1r1; g_a2[row1 * 4 + h] = s2r1; }
        }
    }
}

// ---------------- edge phase: one warp per destination node, 2 passes ----------------
__global__ void k_edge(float* __restrict__ out, int final_layer,
                       const float* __restrict__ pe_next, const int* __restrict__ pos) {
    int gw = (blockIdx.x * blockDim.x + threadIdx.x) >> 5;
    int lane = threadIdx.x & 31;
    if (gw >= NN) return;
    int n = gw;
    int h = lane >> 3;
    float a2h = g_a2[n * 4 + h];
    int beg = g_off[n], end = g_off[n + 1];

    float m = -1e30f, ssum = 0.f;
    #pragma unroll 2
    for (int i = beg; i < end; i++) {
        int s = g_csr_src[i];
        float e = g_a1[s * 4 + h] + a2h;
        e = e > 0.f ? e : 0.2f * e;
        float mn = fmaxf(m, e);
        ssum = ssum * __expf(m - mn) + __expf(e - mn);
        m = mn;
    }
    float inv = ssum > 0.f ? 1.0f / ssum : 0.f;

    float acc[8] = {0, 0, 0, 0, 0, 0, 0, 0};
    #pragma unroll 2
    for (int i = beg; i < end; i++) {
        int s = g_csr_src[i];
        float e = g_a1[s * 4 + h] + a2h;
        e = e > 0.f ? e : 0.2f * e;
        float alpha = __expf(e - m) * inv;
        const float4* p = (const float4*)(g_ft + s * FD + lane * 8);
        float4 u = p[0], w = p[1];
        acc[0] += u.x * alpha; acc[1] += u.y * alpha;
        acc[2] += u.z * alpha; acc[3] += u.w * alpha;
        acc[4] += w.x * alpha; acc[5] += w.y * alpha;
        acc[6] += w.z * alpha; acc[7] += w.w * alpha;
    }

    if (final_layer) {
        #pragma unroll
        for (int j = 0; j < 8; j++) {
            acc[j] += __shfl_xor_sync(0xffffffffu, acc[j], 8);
            acc[j] += __shfl_xor_sync(0xffffffffu, acc[j], 16);
        }
        if (lane < 8) {
            #pragma unroll
            for (int j = 0; j < 8; j++)
                out[n * 64 + lane * 8 + j] = acc[j] * 0.25f;
        }
    } else {
        float* d = g_hcat + n * HSTR + lane * 8;
        #pragma unroll
        for (int j = 0; j < 8; j++) {
            float x = acc[j];
            x = x > 0.f ? x : expm1f(x);              // ELU
            d[j] = __uint_as_float(f2tf32(x));        // pre-round for next GEMM
        }
        g_hcat[n * HSTR + 256 + lane] =
            __uint_as_float(f2tf32(pe_next[pos[n] * 32 + lane]));
    }
}

// ---------------- launcher ----------------
extern "C" void kernel_launch(void* const* d_in, const int* in_sizes, int n_in,
                              void* d_out, int out_size) {
    const float* features = (const float*)d_in[0];
    const float* W0  = (const float*)d_in[1];
    const float* al0 = (const float*)d_in[2];
    const float* ar0 = (const float*)d_in[3];
    const float* pe0 = (const float*)d_in[4];
    const float* W1  = (const float*)d_in[5];
    const float* al1 = (const float*)d_in[6];
    const float* ar1 = (const float*)d_in[7];
    const float* pe1 = (const float*)d_in[8];
    const float* W2  = (const float*)d_in[9];
    const float* al2 = (const float*)d_in[10];
    const float* ar2 = (const float*)d_in[11];
    const float* pe2 = (const float*)d_in[12];
    const int* src = (const int*)d_in[13];
    const int* dst = (const int*)d_in[14];
    const int* pos = (const int*)d_in[15];
    float* out = (float*)d_out;

    float* Wr0 = nullptr; cudaGetSymbolAddress((void**)&Wr0, g_Wr);
    float* Wr1 = Wr0 + 288 * 256;
    float* Wr2 = Wr0 + 2 * 288 * 256;

    dim3 ggrid(2, (NN + BM - 1) / BM);
    int edge_blocks = (NN + 7) / 8;

    // Ordered so the GEMM is the 4th launch (ncu capture lands on it).
    k_copy_feat<<<(NN * 128 + 255) / 256, 256>>>(features);               // 1
    k_fill_pe<<<(NN * 32 + 255) / 256, 256>>>(pe0, pos, 128);             // 2
    k_round_all<<<(288 * 256 + 255) / 256, 256>>>(W0, W1, W2);            // 3
    k_gemm_tf32<<<ggrid, 128>>>(Wr0, 160, al0, ar0);                      // 4  <- profiled

    // CSR build
    k_zero_cnt<<<(NN + 255) / 256, 256>>>();                              // 5
    k_count<<<(EE + 255) / 256, 256>>>(dst);                              // 6
    k_scan<<<1, 1024>>>();                                                // 7
    k_place<<<(EE + 255) / 256, 256>>>(src, dst);                         // 8

    k_edge<<<edge_blocks, 256>>>(out, 0, pe1, pos);                       // 9

    k_gemm_tf32<<<ggrid, 128>>>(Wr1, 288, al1, ar1);                      // 10
    k_edge<<<edge_blocks, 256>>>(out, 0, pe2, pos);                       // 11

    k_gemm_tf32<<<ggrid, 128>>>(Wr2, 288, al2, ar2);                      // 12
    k_edge<<<edge_blocks, 256>>>(out, 1, nullptr, nullptr);               // 13
}

// round 7
// speedup vs baseline: 1.3287x; 1.0367x over previous
#include <cuda_runtime.h>
#include <cuda_bf16.h>
#include <cstdint>

#define NN 30000
#define EE 480000
#define HSTR 288      // hcat row stride (max K)
#define FD 256        // ft row width (H*64)

// ---------------- scratch (device globals; no allocs allowed) ----------------
__device__ float g_hcat[NN * HSTR];     // [h | pe] per layer, tf32-rounded
__device__ float g_ft[NN * FD];         // per-layer transformed features
__device__ float g_Wr[3 * 288 * 256];   // tf32-rounded weights, all layers
__device__ float g_a1[NN * 4];
__device__ float g_a2[NN * 4];
__device__ int   g_cnt[NN];
__device__ int   g_off[NN + 1];
__device__ int   g_csr_src[EE];

__device__ __forceinline__ uint32_t f2tf32(float v) {
    uint32_t t;
    asm("cvt.rna.tf32.f32 %0, %1;" : "=r"(t) : "f"(v));
    return t;
}

// ---------------- hcat assembly (tf32-rounded) ----------------
__global__ void k_copy_feat(const float* __restrict__ f) {
    int i = blockIdx.x * blockDim.x + threadIdx.x;
    if (i < NN * 128) {
        int n = i >> 7, c = i & 127;
        g_hcat[n * HSTR + c] = __uint_as_float(f2tf32(f[i]));
    }
}

__global__ void k_fill_pe(const float* __restrict__ pe, const int* __restrict__ pos, int col0) {
    int i = blockIdx.x * blockDim.x + threadIdx.x;
    if (i < NN * 32) {
        int n = i >> 5, c = i & 31;
        g_hcat[n * HSTR + col0 + c] = __uint_as_float(f2tf32(pe[pos[n] * 32 + c]));
    }
}

__global__ void k_round_all(const float* __restrict__ W0, const float* __restrict__ W1,
                            const float* __restrict__ W2) {
    int i = blockIdx.x * blockDim.x + threadIdx.x;
    const int n0 = 160 * 256, n12 = 288 * 256;
    if (i < n0)
        g_Wr[i] = __uint_as_float(f2tf32(W0[i]));
    if (i < n12) {
        g_Wr[288 * 256 + i]     = __uint_as_float(f2tf32(W1[i]));
        g_Wr[2 * 288 * 256 + i] = __uint_as_float(f2tf32(W2[i]));
    }
}

// ---------------- CSR build ----------------
__global__ void k_zero_cnt() {
    int i = blockIdx.x * blockDim.x + threadIdx.x;
    if (i < NN) g_cnt[i] = 0;
}

__global__ void k_count(const int* __restrict__ dst) {
    int e = blockIdx.x * blockDim.x + threadIdx.x;
    if (e < EE) atomicAdd(&g_cnt[dst[e]], 1);
}

__global__ void k_scan() {
    __shared__ int warp_sums[32];
    __shared__ int s_carry;
    int tid = threadIdx.x;
    int lane = tid & 31, wid = tid >> 5;
    if (tid == 0) s_carry = 0;
    __syncthreads();
    for (int base = 0; base < NN; base += 1024) {
        int i = base + tid;
        int v = (i < NN) ? g_cnt[i] : 0;
        int x = v;
        #pragma unroll
        for (int d = 1; d < 32; d <<= 1) {
            int y = __shfl_up_sync(0xffffffffu, x, d);
            if (lane >= d) x += y;
        }
        if (lane == 31) warp_sums[wid] = x;
        __syncthreads();
        if (wid == 0) {
            int s = warp_sums[lane];
            #pragma unroll
            for (int d = 1; d < 32; d <<= 1) {
                int y = __shfl_up_sync(0xffffffffu, s, d);
                if (lane >= d) s += y;
            }
            warp_sums[lane] = s;
        }
        __syncthreads();
        int carry = s_carry;
        int excl = x - v + (wid > 0 ? warp_sums[wid - 1] : 0);
        if (i < NN) {
            g_off[i] = carry + excl;
            g_cnt[i] = carry + excl;
        }
        int chunk_total = warp_sums[31];
        __syncthreads();
        if (tid == 0) s_carry = carry + chunk_total;
        __syncthreads();
    }
    if (threadIdx.x == 0) g_off[NN] = s_carry;
}

__global__ void k_place(const int* __restrict__ src, const int* __restrict__ dst) {
    int e = blockIdx.x * blockDim.x + threadIdx.x;
    if (e < EE) {
        int p = atomicAdd(&g_cnt[dst[e]], 1);
        g_csr_src[p] = src[e];
    }
}

// ---------------- TF32 GEMM, 3-stage cp.async, fused a1/a2 epilogue ----------------
// Block 128x128, BK=16, 4 warps (2M x 2N), warp tile 64x64. Loads for tile t+2
// are issued before compute of tile t -> a full compute phase covers each load.
#define BM 128
#define BN 128
#define BK 16
#define ASTR 20
#define BSTR 136
#define ABYTES (BM * ASTR * 4)
#define BBYTES (BK * BSTR * 4)
#define GSMEM (3 * (ABYTES + BBYTES))

__device__ __forceinline__ void cpa16(uint32_t dst, const float* src, int sz) {
    asm volatile("cp.async.cg.shared.global [%0], [%1], 16, %2;\n"
                 :: "r"(dst), "l"(src), "r"(sz));
}

__global__ __launch_bounds__(128, 2) void k_gemm_tf32(const float* __restrict__ Wb, int K,
                                                      const float* __restrict__ al,
                                                      const float* __restrict__ ar) {
    extern __shared__ char smem[];
    int bm = blockIdx.y * BM;
    int bn = blockIdx.x * BN;
    int tid = threadIdx.x;
    int lane = tid & 31, warp = tid >> 5;
    int warpM = warp & 1, warpN = warp >> 1;     // 2 x 2
    int gid = lane >> 2, tig = lane & 3;

    float c[4][8][4] = {};

    int arow[4], akq[4], apred[4];
    const float* asrc[4];
    uint32_t adst[4];
    int bkk[4], bnq[4];
    const float* bsrc[4];
    uint32_t bdst[4];
    uint32_t sbase = (uint32_t)__cvta_generic_to_shared(smem);
    #pragma unroll
    for (int j = 0; j < 4; j++) {
        int ch = tid + j * 128;
        arow[j] = ch >> 2; akq[j] = (ch & 3) * 4;
        apred[j] = (bm + arow[j]) < NN ? 16 : 0;
        asrc[j] = g_hcat + (size_t)(apred[j] ? bm + arow[j] : 0) * HSTR + akq[j];
        adst[j] = sbase + (arow[j] * ASTR + akq[j]) * 4;
        bkk[j] = ch >> 5; bnq[j] = (ch & 31) * 4;
        bsrc[j] = Wb + bkk[j] * 256 + bn + bnq[j];
        bdst[j] = sbase + 3 * ABYTES + (bkk[j] * BSTR + bnq[j]) * 4;
    }

    int T = K / BK;

    // prologue: tiles 0 and 1
    #pragma unroll
    for (int j = 0; j < 4; j++) cpa16(adst[j], asrc[j], apred[j]);
    #pragma unroll
    for (int j = 0; j < 4; j++) cpa16(bdst[j], bsrc[j], 16);
    asm volatile("cp.async.commit_group;\n");
    if (T > 1) {
        #pragma unroll
        for (int j = 0; j < 4; j++) cpa16(adst[j] + ABYTES, asrc[j] + BK, apred[j]);
        #pragma unroll
        for (int j = 0; j < 4; j++) cpa16(bdst[j] + BBYTES, bsrc[j] + BK * 256, 16);
        asm volatile("cp.async.commit_group;\n");
    }

    for (int t = 0; t < T; t++) {
        if (t + 1 < T)
            asm volatile("cp.async.wait_group 1;\n");
        else
            asm volatile("cp.async.wait_group 0;\n");
        __syncthreads();

        // issue loads for tile t+2 into buffer (t+2)%3 (compute of t covers them)
        if (t + 2 < T) {
            int st = (t + 2) % 3;
            int k0 = (t + 2) * BK;
            #pragma unroll
            for (int j = 0; j < 4; j++) cpa16(adst[j] + st * ABYTES, asrc[j] + k0, apred[j]);
            #pragma unroll
            for (int j = 0; j < 4; j++) cpa16(bdst[j] + st * BBYTES, bsrc[j] + k0 * 256, 16);
            asm volatile("cp.async.commit_group;\n");
        }

        const float* Ac = (const float*)(smem + (t % 3) * ABYTES);
        const float* Bc = (const float*)(smem + 3 * ABYTES + (t % 3) * BBYTES);
        #pragma unroll
        for (int ks = 0; ks < BK; ks += 8) {
            uint32_t a[4][4], b[8][2];
            #pragma unroll
            for (int mt = 0; mt < 4; mt++) {
                int m0 = warpM * 64 + mt * 16 + gid;
                a[mt][0] = __float_as_uint(Ac[m0 * ASTR + ks + tig]);
                a[mt][1] = __float_as_uint(Ac[(m0 + 8) * ASTR + ks + tig]);
                a[mt][2] = __float_as_uint(Ac[m0 * ASTR + ks + tig + 4]);
                a[mt][3] = __float_as_uint(Ac[(m0 + 8) * ASTR + ks + tig + 4]);
            }
            #pragma unroll
            for (int nt = 0; nt < 8; nt++) {
                int n0 = warpN * 64 + nt * 8 + gid;
                b[nt][0] = __float_as_uint(Bc[(ks + tig) * BSTR + n0]);
                b[nt][1] = __float_as_uint(Bc[(ks + tig + 4) * BSTR + n0]);
            }
            #pragma unroll
            for (int mt = 0; mt < 4; mt++)
                #pragma unroll
                for (int nt = 0; nt < 8; nt++)
                    asm volatile(
                        "mma.sync.aligned.m16n8k8.row.col.f32.tf32.tf32.f32 "
                        "{%0,%1,%2,%3}, {%4,%5,%6,%7}, {%8,%9}, {%0,%1,%2,%3};"
                        : "+f"(c[mt][nt][0]), "+f"(c[mt][nt][1]),
                          "+f"(c[mt][nt][2]), "+f"(c[mt][nt][3])
                        : "r"(a[mt][0]), "r"(a[mt][1]), "r"(a[mt][2]), "r"(a[mt][3]),
                          "r"(b[nt][0]), "r"(b[nt][1]));
        }
        __syncthreads();
    }

    // epilogue: store ft + fused a1/a2 row-dots (warp tile = one head's 64 cols)
    int h = blockIdx.x * 2 + warpN;
    const float* alh = al + h * 64;
    const float* arh = ar + h * 64;
    float lw[8][2], rw[8][2];
    #pragma unroll
    for (int nt = 0; nt < 8; nt++) {
        int c64 = nt * 8 + tig * 2;
        lw[nt][0] = alh[c64]; lw[nt][1] = alh[c64 + 1];
        rw[nt][0] = arh[c64]; rw[nt][1] = arh[c64 + 1];
    }
    #pragma unroll
    for (int mt = 0; mt < 4; mt++) {
        int row0 = bm + warpM * 64 + mt * 16 + gid;
        int row1 = row0 + 8;
        float s1r0 = 0.f, s2r0 = 0.f, s1r1 = 0.f, s2r1 = 0.f;
        #pragma unroll
        for (int nt = 0; nt < 8; nt++) {
            int col = bn + warpN * 64 + nt * 8 + tig * 2;
            s1r0 += c[mt][nt][0] * lw[nt][0] + c[mt][nt][1] * lw[nt][1];
            s2r0 += c[mt][nt][0] * rw[nt][0] + c[mt][nt][1] * rw[nt][1];
            s1r1 += c[mt][nt][2] * lw[nt][0] + c[mt][nt][3] * lw[nt][1];
            s2r1 += c[mt][nt][2] * rw[nt][0] + c[mt][nt][3] * rw[nt][1];
            if (row0 < NN)
                *(float2*)(g_ft + row0 * FD + col) = make_float2(c[mt][nt][0], c[mt][nt][1]);
            if (row1 < NN)
                *(float2*)(g_ft + row1 * FD + col) = make_float2(c[mt][nt][2], c[mt][nt][3]);
        }
        #pragma unroll
        for (int d = 1; d < 4; d <<= 1) {
            s1r0 += __shfl_xor_sync(0xffffffffu, s1r0, d);
            s2r0 += __shfl_xor_sync(0xffffffffu, s2r0, d);
            s1r1 += __shfl_xor_sync(0xffffffffu, s1r1, d);
            s2r1 += __shfl_xor_sync(0xffffffffu, s2r1, d);
        }
        if (tig == 0) {
            if (row0 < NN) { g_a1[row0 * 4 + h] = s1r0; g_a2[row0 * 4 + h] = s2r0; }
            if (row1 < NN) { g_a1[row1 * 4 + h] = s1r1; g_a2[row1 * 4 + h] = s2r1; }
        }
    }
}

// ---------------- edge phase: single-pass online softmax, one warp per dst ----------------
__global__ void k_edge(float* __restrict__ out, int final_layer,
                       const float* __restrict__ pe_next, const int* __restrict__ pos) {
    int gw = (blockIdx.x * blockDim.x + threadIdx.x) >> 5;
    int lane = threadIdx.x & 31;
    if (gw >= NN) return;
    int n = gw;
    int h = lane >> 3;
    float a2h = g_a2[n * 4 + h];
    int beg = g_off[n], end = g_off[n + 1];

    float m = -1e30f, ssum = 0.f;
    float acc[8] = {0, 0, 0, 0, 0, 0, 0, 0};

    if (beg < end) {
        int s = g_csr_src[beg];
        float a1v = g_a1[s * 4 + h];
        for (int i = beg; i < end; i++) {
            // prefetch next edge's src + a1 before the heavy gather
            int s_nxt = 0; float a1_nxt = 0.f;
            if (i + 1 < end) {
                s_nxt = g_csr_src[i + 1];
                a1_nxt = g_a1[s_nxt * 4 + h];
            }
            float e = a1v + a2h;
            e = e > 0.f ? e : 0.2f * e;
            float mn = fmaxf(m, e);
            float sc = __expf(m - mn);       // 0 on first iter (m = -1e30)
            float f = __expf(e - mn);
            ssum = ssum * sc + f;
            m = mn;
            const float4* p = (const float4*)(g_ft + (size_t)s * FD + lane * 8);
            float4 u = p[0], ww = p[1];
            acc[0] = acc[0] * sc + u.x * f;  acc[1] = acc[1] * sc + u.y * f;
            acc[2] = acc[2] * sc + u.z * f;  acc[3] = acc[3] * sc + u.w * f;
            acc[4] = acc[4] * sc + ww.x * f; acc[5] = acc[5] * sc + ww.y * f;
            acc[6] = acc[6] * sc + ww.z * f; acc[7] = acc[7] * sc + ww.w * f;
            s = s_nxt; a1v = a1_nxt;
        }
    }
    float inv = ssum > 0.f ? 1.0f / ssum : 0.f;
    #pragma unroll
    for (int j = 0; j < 8; j++) acc[j] *= inv;

    if (final_layer) {
        #pragma unroll
        for (int j = 0; j < 8; j++) {
            acc[j] += __shfl_xor_sync(0xffffffffu, acc[j], 8);
            acc[j] += __shfl_xor_sync(0xffffffffu, acc[j], 16);
        }
        if (lane < 8) {
            #pragma unroll
            for (int j = 0; j < 8; j++)
                out[n * 64 + lane * 8 + j] = acc[j] * 0.25f;
        }
    } else {
        float* d = g_hcat + n * HSTR + lane * 8;
        #pragma unroll
        for (int j = 0; j < 8; j++) {
            float x = acc[j];
            x = x > 0.f ? x : expm1f(x);              // ELU
            d[j] = __uint_as_float(f2tf32(x));        // pre-round for next GEMM
        }
        g_hcat[n * HSTR + 256 + lane] =
            __uint_as_float(f2tf32(pe_next[pos[n] * 32 + lane]));
    }
}

// ---------------- launcher ----------------
extern "C" void kernel_launch(void* const* d_in, const int* in_sizes, int n_in,
                              void* d_out, int out_size) {
    const float* features = (const float*)d_in[0];
    const float* W0  = (const float*)d_in[1];
    const float* al0 = (const float*)d_in[2];
    const float* ar0 = (const float*)d_in[3];
    const float* pe0 = (const float*)d_in[4];
    const float* W1  = (const float*)d_in[5];
    const float* al1 = (const float*)d_in[6];
    const float* ar1 = (const float*)d_in[7];
    const float* pe1 = (const float*)d_in[8];
    const float* W2  = (const float*)d_in[9];
    const float* al2 = (const float*)d_in[10];
    const float* ar2 = (const float*)d_in[11];
    const float* pe2 = (const float*)d_in[12];
    const int* src = (const int*)d_in[13];
    const int* dst = (const int*)d_in[14];
    const int* pos = (const int*)d_in[15];
    float* out = (float*)d_out;

    float* Wr0 = nullptr; cudaGetSymbolAddress((void**)&Wr0, g_Wr);
    float* Wr1 = Wr0 + 288 * 256;
    float* Wr2 = Wr0 + 2 * 288 * 256;

    cudaFuncSetAttribute(k_gemm_tf32, cudaFuncAttributeMaxDynamicSharedMemorySize, GSMEM);

    dim3 ggrid(2, (NN + BM - 1) / BM);
    int edge_blocks = (NN + 7) / 8;

    // Ordered so the GEMM is the 4th launch (ncu capture lands on it).
    k_copy_feat<<<(NN * 128 + 255) / 256, 256>>>(features);               // 1
    k_fill_pe<<<(NN * 32 + 255) / 256, 256>>>(pe0, pos, 128);             // 2
    k_round_all<<<(288 * 256 + 255) / 256, 256>>>(W0, W1, W2);            // 3
    k_gemm_tf32<<<ggrid, 128, GSMEM>>>(Wr0, 160, al0, ar0);               // 4  <- profiled

    // CSR build
    k_zero_cnt<<<(NN + 255) / 256, 256>>>();                              // 5
    k_count<<<(EE + 255) / 256, 256>>>(dst);                              // 6
    k_scan<<<1, 1024>>>();                                                // 7
    k_place<<<(EE + 255) / 256, 256>>>(src, dst);                         // 8

    k_edge<<<edge_blocks, 256>>>(out, 0, pe1, pos);                       // 9

    k_gemm_tf32<<<ggrid, 128, GSMEM>>>(Wr1, 288, al1, ar1);               // 10
    k_edge<<<edge_blocks, 256>>>(out, 0, pe2, pos);                       // 11

    k_gemm_tf32<<<ggrid, 128, GSMEM>>>(Wr2, 288, al2, ar2);               // 12
    k_edge<<<edge_blocks, 256>>>(out, 1, nullptr, nullptr);               // 13
}